// round 1
// baseline (speedup 1.0000x reference)
#include <cuda_runtime.h>
#include <cstdint>

#define NHITS 80000
#define KOBJ  512
#define EPSF  1e-9f

// ---------------- device scratch (no allocations allowed) ----------------
__device__ unsigned long long g_packed[KOBJ];   // (beta_bits<<32)|(~n) argmax
__device__ int    g_cnt[KOBJ];
__device__ float  g_num[KOBJ];
__device__ float  g_den[KOBJ];
__device__ float  g_q[NHITS];
__device__ float4 g_obj[KOBJ];                  // x, y, q_alpha/(N-cnt+eps), q_alpha/(cnt+eps)
__device__ float  g_scal[8];                    // 0:noise_beta 1:noise_cnt 2:cc_sum 3:pot_sum 4:(beta+pay)sum 5:inv_nobj

// ---------------- helpers ----------------
__device__ __forceinline__ float softclipf(float x, float s) {
    float y = x / s;
    y = (y > 1.0f) ? logf(y + 1.0f) : y;
    return y * s;
}
__device__ __forceinline__ float huberf(float x, float d) {
    float ax = fabsf(x);
    return (ax < d) ? x * x : d * d + 2.0f * d * (ax - d);
}
__device__ __forceinline__ float warpSum(float v) {
    #pragma unroll
    for (int o = 16; o > 0; o >>= 1) v += __shfl_down_sync(0xffffffffu, v, o);
    return v;
}
__device__ __forceinline__ float sqrt_approx(float x) {
    float r;
    asm("sqrt.approx.f32 %0, %1;" : "=f"(r) : "f"(x));
    return r;
}

// ---------------- phase 0: zero scratch ----------------
__global__ void k_zero() {
    int i = threadIdx.x;
    g_cnt[i] = 0;
    g_packed[i] = 0ull;
    g_num[i] = 0.0f;
    g_den[i] = 0.0f;
    if (i < 8) g_scal[i] = 0.0f;
}

// ---------------- phase 1: per-hit pass ----------------
__global__ void __launch_bounds__(256) k_phase1(
    const float* __restrict__ pb, const float* __restrict__ cc,
    const float* __restrict__ pE, const float* __restrict__ pPos,
    const float* __restrict__ pT, const float* __restrict__ pId,
    const int*   __restrict__ tIdx, const float* __restrict__ tE,
    const float* __restrict__ tPos, const float* __restrict__ tT)
{
    int n = blockIdx.x * blockDim.x + threadIdx.x;
    float nb = 0.0f, ncnt = 0.0f, ccs = 0.0f;
    if (n < NHITS) {
        float b = fminf(fmaxf(pb[n], 1e-6f), 1.0f - 1e-6f);
        float at = atanhf(b);
        float q = at * at + 0.1f;
        g_q[n] = q;
        float x = cc[2 * n], y = cc[2 * n + 1];
        ccs = x * x + y * y;
        int t = tIdx[n];
        if (t >= 0) {
            atomicAdd(&g_cnt[t], 1);
            unsigned long long pk =
                ((unsigned long long)__float_as_uint(b) << 32) |
                (unsigned long long)(0xFFFFFFFFu - (unsigned)n);
            atomicMax(&g_packed[t], pk);
            // payload losses
            float te = tE[n];
            float ed = fabsf(te - pE[n]);
            float le = 10.0f * expf(-0.1f * ed * ed) + 0.01f * ed;
            le = softclipf(le, 10.0f);
            float dpx = tPos[2 * n]     - pPos[2 * n];
            float dpy = tPos[2 * n + 1] - pPos[2 * n + 1];
            float d2p = dpx * dpx + dpy * dpy;
            float pl = softclipf(huberf(sqrtf(d2p * 0.01f + 0.01f), 10.0f), 3.0f);
            float tl = softclipf(huberf(tT[n] - pT[n], 2.0f), 6.0f);
            float cls = 0.0f;
            #pragma unroll
            for (int j = 0; j < 6; j++) { float v = pId[6 * n + j]; cls += v * v; }
            cls *= (1e-8f / 6.0f);
            float payload = le + pl + tl + cls;
            float ew = (te > 10.0f) ? 1.0f : fmaxf((te - 0.5f) * (1.0f / 9.5f), 0.0f);
            float pw = b * ew;
            atomicAdd(&g_num[t], payload * pw);
            atomicAdd(&g_den[t], pw);
        } else {
            nb = b; ncnt = 1.0f;
        }
    }
    // block-reduce noise_beta, noise_cnt, cc_sum
    __shared__ float sr[3][8];
    float w0 = warpSum(nb), w1 = warpSum(ncnt), w2 = warpSum(ccs);
    int lane = threadIdx.x & 31, wid = threadIdx.x >> 5;
    if (lane == 0) { sr[0][wid] = w0; sr[1][wid] = w1; sr[2][wid] = w2; }
    __syncthreads();
    if (wid == 0) {
        float v0 = (lane < 8) ? sr[0][lane] : 0.0f;
        float v1 = (lane < 8) ? sr[1][lane] : 0.0f;
        float v2 = (lane < 8) ? sr[2][lane] : 0.0f;
        v0 = warpSum(v0); v1 = warpSum(v1); v2 = warpSum(v2);
        if (lane == 0) {
            if (v1 != 0.0f || v0 != 0.0f) {
                atomicAdd(&g_scal[0], v0);
                atomicAdd(&g_scal[1], v1);
            }
            atomicAdd(&g_scal[2], v2);
        }
    }
}

// ---------------- phase 2: per-object (K=512, one block) ----------------
__global__ void k_phase2(const float* __restrict__ cc) {
    int k = threadIdx.x;
    int cnt = g_cnt[k];
    float4 o = make_float4(0.0f, 0.0f, 0.0f, 0.0f);
    float part = 0.0f, nob = 0.0f;
    if (cnt > 0) {
        unsigned long long p = g_packed[k];
        float betaA = __uint_as_float((unsigned)(p >> 32));
        unsigned alpha = 0xFFFFFFFFu - (unsigned)(p & 0xFFFFFFFFull);
        o.x = cc[2 * alpha];
        o.y = cc[2 * alpha + 1];
        float at = atanhf(betaA);
        float qa = at * at + 0.1f;
        o.z = qa / ((float)NHITS - (float)cnt + EPSF);  // repulsion weight
        o.w = qa / ((float)cnt + EPSF);                 // attraction weight
        part = (1.0f - betaA) + g_num[k] / (g_den[k] + EPSF);
        nob = 1.0f;
    }
    g_obj[k] = o;
    __shared__ float sp[16], sn[16];
    float w0 = warpSum(part), w1 = warpSum(nob);
    int lane = threadIdx.x & 31, wid = threadIdx.x >> 5;
    if (lane == 0) { sp[wid] = w0; sn[wid] = w1; }
    __syncthreads();
    if (wid == 0) {
        float v0 = (lane < 16) ? sp[lane] : 0.0f;
        float v1 = (lane < 16) ? sn[lane] : 0.0f;
        v0 = warpSum(v0); v1 = warpSum(v1);
        if (lane == 0) {
            g_scal[4] = v0;
            g_scal[5] = 1.0f / (v1 + EPSF);
        }
    }
}

// ---------------- phase 3: dense N x K repulsion + sparse attraction ----------------
__global__ void __launch_bounds__(256) k_phase3(
    const float* __restrict__ cc, const int* __restrict__ tIdx)
{
    __shared__ float4 sobj[KOBJ];
    for (int i = threadIdx.x; i < KOBJ; i += blockDim.x) sobj[i] = g_obj[i];
    __syncthreads();

    int n = blockIdx.x * blockDim.x + threadIdx.x;
    float res = 0.0f;
    if (n < NHITS) {
        float x = cc[2 * n], y = cc[2 * n + 1];
        float q = g_q[n];
        float a0 = 0.0f, a1 = 0.0f, a2 = 0.0f, a3 = 0.0f;
        #pragma unroll 4
        for (int k = 0; k < KOBJ; k += 4) {
            {
                float4 o = sobj[k];
                float dx = x - o.x, dy = y - o.y;
                float d2 = fmaf(dx, dx, 1e-6f); d2 = fmaf(dy, dy, d2);
                float d = sqrt_approx(d2);
                a0 = fmaf(fmaxf(1.0f - d, 0.0f), o.z, a0);
            }
            {
                float4 o = sobj[k + 1];
                float dx = x - o.x, dy = y - o.y;
                float d2 = fmaf(dx, dx, 1e-6f); d2 = fmaf(dy, dy, d2);
                float d = sqrt_approx(d2);
                a1 = fmaf(fmaxf(1.0f - d, 0.0f), o.z, a1);
            }
            {
                float4 o = sobj[k + 2];
                float dx = x - o.x, dy = y - o.y;
                float d2 = fmaf(dx, dx, 1e-6f); d2 = fmaf(dy, dy, d2);
                float d = sqrt_approx(d2);
                a2 = fmaf(fmaxf(1.0f - d, 0.0f), o.z, a2);
            }
            {
                float4 o = sobj[k + 3];
                float dx = x - o.x, dy = y - o.y;
                float d2 = fmaf(dx, dx, 1e-6f); d2 = fmaf(dy, dy, d2);
                float d = sqrt_approx(d2);
                a3 = fmaf(fmaxf(1.0f - d, 0.0f), o.z, a3);
            }
        }
        res = ((a0 + a1) + (a2 + a3)) * q;
        int t = tIdx[n];
        if (t >= 0) {
            // subtract own-object repulsion term (the (1-Mf) exclusion), add attraction
            float4 o = sobj[t];
            float dx = x - o.x, dy = y - o.y;
            float d2n = dx * dx + dy * dy;
            float d = sqrt_approx(d2n + 1e-6f);
            res -= fmaxf(1.0f - d, 0.0f) * o.z * q;
            res = fmaf(d2n * o.w, q, res);
        }
    }
    __shared__ float sr[8];
    float w = warpSum(res);
    int lane = threadIdx.x & 31, wid = threadIdx.x >> 5;
    if (lane == 0) sr[wid] = w;
    __syncthreads();
    if (wid == 0) {
        float v = (lane < 8) ? sr[lane] : 0.0f;
        v = warpSum(v);
        if (lane == 0) atomicAdd(&g_scal[3], v);
    }
}

// ---------------- phase 4: final combine ----------------
__global__ void k_phase4(float* __restrict__ out) {
    float inv = g_scal[5];
    float total = (g_scal[3] + g_scal[4]) * inv
                + g_scal[0] / (g_scal[1] + EPSF)
                + 0.001f * g_scal[2] * (1.0f / ((float)NHITS * 2.0f));
    out[0] = total;
}

// ---------------- launch ----------------
extern "C" void kernel_launch(void* const* d_in, const int* in_sizes, int n_in,
                              void* d_out, int out_size)
{
    const float* pb   = (const float*)d_in[0];   // pred_beta    (N,1)
    const float* cc   = (const float*)d_in[1];   // pred_ccoords (N,2)
    const float* pE   = (const float*)d_in[2];   // pred_energy  (N,1)
    const float* pPos = (const float*)d_in[3];   // pred_pos     (N,2)
    const float* pT   = (const float*)d_in[4];   // pred_time    (N,1)
    const float* pId  = (const float*)d_in[5];   // pred_id      (N,6)
    const int*   tIdx = (const int*)  d_in[6];   // t_idx        (N,1)
    const float* tE   = (const float*)d_in[7];   // t_energy     (N,1)
    const float* tPos = (const float*)d_in[8];   // t_pos        (N,2)
    const float* tT   = (const float*)d_in[9];   // t_time       (N,1)
    // d_in[10] = t_pid (unused by the math)
    float* out = (float*)d_out;

    k_zero<<<1, KOBJ>>>();
    int nb1 = (NHITS + 255) / 256;
    k_phase1<<<nb1, 256>>>(pb, cc, pE, pPos, pT, pId, tIdx, tE, tPos, tT);
    k_phase2<<<1, KOBJ>>>(cc);
    k_phase3<<<nb1, 256>>>(cc, tIdx);
    k_phase4<<<1, 1>>>(out);
}

// round 2
// speedup vs baseline: 1.0901x; 1.0901x over previous
#include <cuda_runtime.h>
#include <cstdint>

#define NHITS 80000
#define KOBJ  512
#define KCHUNK 128
#define NCHUNK (KOBJ / KCHUNK)
#define EPSF  1e-9f

#define NBX 313               // ceil(80000/256)
#define TOTAL_P3_BLOCKS (NBX * NCHUNK)

// ---------------- device scratch (zero-initialized at module load; every run
// re-zeroes it in the final block, so the invariant holds across replays) ----
__device__ unsigned long long g_packed[KOBJ];   // (beta_bits<<32)|(~n) argmax
__device__ int    g_cnt[KOBJ];
__device__ float  g_num[KOBJ];
__device__ float  g_den[KOBJ];
__device__ float  g_q[NHITS];
__device__ float4 g_obj[KOBJ];                  // (-2ox, -2oy, ox^2+oy^2+1e-6, rep_w)
__device__ float  g_attw[KOBJ];                 // attraction weight q_a/(cnt+eps)
__device__ float  g_scal[8];                    // 0:noise_b 1:noise_cnt 2:cc 3:pot 4:beta+pay 5:inv_nobj
__device__ unsigned g_ticket;

// ---------------- helpers ----------------
__device__ __forceinline__ float softclipf(float x, float s) {
    float y = x / s;
    y = (y > 1.0f) ? logf(y + 1.0f) : y;
    return y * s;
}
__device__ __forceinline__ float huberf(float x, float d) {
    float ax = fabsf(x);
    return (ax < d) ? x * x : d * d + 2.0f * d * (ax - d);
}
__device__ __forceinline__ float warpSum(float v) {
    #pragma unroll
    for (int o = 16; o > 0; o >>= 1) v += __shfl_down_sync(0xffffffffu, v, o);
    return v;
}
__device__ __forceinline__ float sqrt_approx(float x) {
    float r;
    asm("sqrt.approx.f32 %0, %1;" : "=f"(r) : "f"(x));
    return r;
}

// ---------------- phase 1: per-hit pass (scratch pre-zeroed) ----------------
__global__ void __launch_bounds__(256) k_phase1(
    const float* __restrict__ pb, const float* __restrict__ cc,
    const float* __restrict__ pE, const float* __restrict__ pPos,
    const float* __restrict__ pT, const float* __restrict__ pId,
    const int*   __restrict__ tIdx, const float* __restrict__ tE,
    const float* __restrict__ tPos, const float* __restrict__ tT)
{
    int n = blockIdx.x * blockDim.x + threadIdx.x;
    float nb = 0.0f, ncnt = 0.0f, ccs = 0.0f;
    if (n < NHITS) {
        float b = fminf(fmaxf(pb[n], 1e-6f), 1.0f - 1e-6f);
        float at = atanhf(b);
        float q = at * at + 0.1f;
        g_q[n] = q;
        float x = cc[2 * n], y = cc[2 * n + 1];
        ccs = x * x + y * y;
        int t = tIdx[n];
        if (t >= 0) {
            atomicAdd(&g_cnt[t], 1);
            unsigned long long pk =
                ((unsigned long long)__float_as_uint(b) << 32) |
                (unsigned long long)(0xFFFFFFFFu - (unsigned)n);
            atomicMax(&g_packed[t], pk);
            float te = tE[n];
            float ed = fabsf(te - pE[n]);
            float le = 10.0f * expf(-0.1f * ed * ed) + 0.01f * ed;
            le = softclipf(le, 10.0f);
            float dpx = tPos[2 * n]     - pPos[2 * n];
            float dpy = tPos[2 * n + 1] - pPos[2 * n + 1];
            float d2p = dpx * dpx + dpy * dpy;
            float pl = softclipf(huberf(sqrtf(d2p * 0.01f + 0.01f), 10.0f), 3.0f);
            float tl = softclipf(huberf(tT[n] - pT[n], 2.0f), 6.0f);
            float cls = 0.0f;
            #pragma unroll
            for (int j = 0; j < 6; j++) { float v = pId[6 * n + j]; cls += v * v; }
            cls *= (1e-8f / 6.0f);
            float payload = le + pl + tl + cls;
            float ew = (te > 10.0f) ? 1.0f : fmaxf((te - 0.5f) * (1.0f / 9.5f), 0.0f);
            float pw = b * ew;
            atomicAdd(&g_num[t], payload * pw);
            atomicAdd(&g_den[t], pw);
        } else {
            nb = b; ncnt = 1.0f;
        }
    }
    __shared__ float sr[3][8];
    float w0 = warpSum(nb), w1 = warpSum(ncnt), w2 = warpSum(ccs);
    int lane = threadIdx.x & 31, wid = threadIdx.x >> 5;
    if (lane == 0) { sr[0][wid] = w0; sr[1][wid] = w1; sr[2][wid] = w2; }
    __syncthreads();
    if (wid == 0) {
        float v0 = (lane < 8) ? sr[0][lane] : 0.0f;
        float v1 = (lane < 8) ? sr[1][lane] : 0.0f;
        float v2 = (lane < 8) ? sr[2][lane] : 0.0f;
        v0 = warpSum(v0); v1 = warpSum(v1); v2 = warpSum(v2);
        if (lane == 0) {
            if (v1 != 0.0f || v0 != 0.0f) {
                atomicAdd(&g_scal[0], v0);
                atomicAdd(&g_scal[1], v1);
            }
            atomicAdd(&g_scal[2], v2);
        }
    }
}

// ---------------- phase 2: per-object (K=512, one block) ----------------
__global__ void k_phase2(const float* __restrict__ cc) {
    int k = threadIdx.x;
    int cnt = g_cnt[k];
    float4 o = make_float4(0.0f, 0.0f, 1e6f, 0.0f);  // far dummy point, zero weight
    float aw = 0.0f;
    float part = 0.0f, nob = 0.0f;
    if (cnt > 0) {
        unsigned long long p = g_packed[k];
        float betaA = __uint_as_float((unsigned)(p >> 32));
        unsigned alpha = 0xFFFFFFFFu - (unsigned)(p & 0xFFFFFFFFull);
        float ox = cc[2 * alpha], oy = cc[2 * alpha + 1];
        float at = atanhf(betaA);
        float qa = at * at + 0.1f;
        o.x = -2.0f * ox;
        o.y = -2.0f * oy;
        o.z = ox * ox + oy * oy + 1e-6f;
        o.w = qa / ((float)NHITS - (float)cnt + EPSF);  // repulsion weight
        aw  = qa / ((float)cnt + EPSF);                 // attraction weight
        part = (1.0f - betaA) + g_num[k] / (g_den[k] + EPSF);
        nob = 1.0f;
    }
    g_obj[k] = o;
    g_attw[k] = aw;
    __shared__ float sp[16], sn[16];
    float w0 = warpSum(part), w1 = warpSum(nob);
    int lane = threadIdx.x & 31, wid = threadIdx.x >> 5;
    if (lane == 0) { sp[wid] = w0; sn[wid] = w1; }
    __syncthreads();
    if (wid == 0) {
        float v0 = (lane < 16) ? sp[lane] : 0.0f;
        float v1 = (lane < 16) ? sn[lane] : 0.0f;
        v0 = warpSum(v0); v1 = warpSum(v1);
        if (lane == 0) {
            g_scal[4] = v0;
            g_scal[5] = 1.0f / (v1 + EPSF);
        }
    }
}

// ---------------- phase 3: dense N x K/4 per block + last-block finalize ----
__global__ void __launch_bounds__(256) k_phase3(
    const float* __restrict__ cc, const int* __restrict__ tIdx,
    float* __restrict__ out)
{
    __shared__ float4 sobj[KCHUNK];
    const int kbase = blockIdx.y * KCHUNK;
    for (int i = threadIdx.x; i < KCHUNK; i += blockDim.x) sobj[i] = g_obj[kbase + i];
    __syncthreads();

    int n = blockIdx.x * blockDim.x + threadIdx.x;
    float res = 0.0f;
    if (n < NHITS) {
        float x = cc[2 * n], y = cc[2 * n + 1];
        float q = g_q[n];
        float h = fmaf(x, x, y * y);            // |x|^2
        float a0 = 0.0f, a1 = 0.0f, a2 = 0.0f, a3 = 0.0f;
        #pragma unroll 4
        for (int k = 0; k < KCHUNK; k += 4) {
            {
                float4 o = sobj[k];
                float t = fmaf(o.x, x, o.z); t = fmaf(o.y, y, t);
                float d = sqrt_approx(h + t);
                a0 = fmaf(fmaxf(1.0f - d, 0.0f), o.w, a0);
            }
            {
                float4 o = sobj[k + 1];
                float t = fmaf(o.x, x, o.z); t = fmaf(o.y, y, t);
                float d = sqrt_approx(h + t);
                a1 = fmaf(fmaxf(1.0f - d, 0.0f), o.w, a1);
            }
            {
                float4 o = sobj[k + 2];
                float t = fmaf(o.x, x, o.z); t = fmaf(o.y, y, t);
                float d = sqrt_approx(h + t);
                a2 = fmaf(fmaxf(1.0f - d, 0.0f), o.w, a2);
            }
            {
                float4 o = sobj[k + 3];
                float t = fmaf(o.x, x, o.z); t = fmaf(o.y, y, t);
                float d = sqrt_approx(h + t);
                a3 = fmaf(fmaxf(1.0f - d, 0.0f), o.w, a3);
            }
        }
        res = ((a0 + a1) + (a2 + a3)) * q;
        int t = tIdx[n];
        if (t >= kbase && t < kbase + KCHUNK) {
            // own-object correction: remove its repulsion term, add attraction
            float4 o = sobj[t - kbase];
            float dx = fmaf(0.5f, o.x, x);      // x - ox
            float dy = fmaf(0.5f, o.y, y);      // y - oy
            float d2n = fmaf(dx, dx, dy * dy);  // exact d2 (no eps)
            float d = sqrt_approx(d2n + 1e-6f);
            res -= fmaxf(1.0f - d, 0.0f) * o.w * q;
            res = fmaf(d2n * g_attw[t], q, res);
        }
    }
    __shared__ float sr[8];
    float w = warpSum(res);
    int lane = threadIdx.x & 31, wid = threadIdx.x >> 5;
    if (lane == 0) sr[wid] = w;
    __syncthreads();
    __shared__ bool isLast;
    if (threadIdx.x == 0) isLast = false;
    if (wid == 0) {
        float v = (lane < 8) ? sr[lane] : 0.0f;
        v = warpSum(v);
        if (lane == 0) {
            atomicAdd(&g_scal[3], v);
            __threadfence();
            unsigned tk = atomicAdd(&g_ticket, 1u);
            isLast = (tk == (unsigned)(TOTAL_P3_BLOCKS - 1));
        }
    }
    __syncthreads();
    if (isLast) {
        if (threadIdx.x == 0) {
            float inv = g_scal[5];
            float total = (g_scal[3] + g_scal[4]) * inv
                        + g_scal[0] / (g_scal[1] + EPSF)
                        + 0.001f * g_scal[2] * (1.0f / ((float)NHITS * 2.0f));
            out[0] = total;
            g_ticket = 0;
        }
        // re-zero scratch for the next invocation
        for (int i = threadIdx.x; i < KOBJ; i += blockDim.x) {
            g_cnt[i] = 0;
            g_packed[i] = 0ull;
            g_num[i] = 0.0f;
            g_den[i] = 0.0f;
        }
        if (threadIdx.x < 8) g_scal[threadIdx.x] = 0.0f;
    }
}

// ---------------- launch ----------------
extern "C" void kernel_launch(void* const* d_in, const int* in_sizes, int n_in,
                              void* d_out, int out_size)
{
    const float* pb   = (const float*)d_in[0];
    const float* cc   = (const float*)d_in[1];
    const float* pE   = (const float*)d_in[2];
    const float* pPos = (const float*)d_in[3];
    const float* pT   = (const float*)d_in[4];
    const float* pId  = (const float*)d_in[5];
    const int*   tIdx = (const int*)  d_in[6];
    const float* tE   = (const float*)d_in[7];
    const float* tPos = (const float*)d_in[8];
    const float* tT   = (const float*)d_in[9];
    float* out = (float*)d_out;

    k_phase1<<<NBX, 256>>>(pb, cc, pE, pPos, pT, pId, tIdx, tE, tPos, tT);
    k_phase2<<<1, KOBJ>>>(cc);
    dim3 g3(NBX, NCHUNK);
    k_phase3<<<g3, 256>>>(cc, tIdx, out);
}

// round 4
// speedup vs baseline: 1.5994x; 1.4672x over previous
#include <cuda_runtime.h>
#include <cstdint>

#define NHITS 80000
#define KOBJ  512
#define NREP  32
#define KCHUNK 64
#define NCHUNK (KOBJ / KCHUNK)
#define EPSF  1e-9f

#define NBX 313               // ceil(80000/256)
#define TOTAL_P3_BLOCKS (NBX * NCHUNK)
#define SCRATCH_TOT (NREP * KOBJ)                     // 16384
#define ZERO_PER_BLOCK ((SCRATCH_TOT + TOTAL_P3_BLOCKS - 1) / TOTAL_P3_BLOCKS) // 7

// ---------------- device scratch (zero at load; re-zeroed by phase3 each run)
__device__ unsigned long long g_packed[NREP][KOBJ];
__device__ int    g_cnt[NREP][KOBJ];
__device__ float  g_num[NREP][KOBJ];
__device__ float  g_den[NREP][KOBJ];
__device__ float  g_q[NHITS];
__device__ float4 g_obj[KOBJ];    // (-2ox, -2oy, ox^2+oy^2+1e-6, rep_w)
__device__ float  g_attw[KOBJ];
__device__ float  g_scal[8];      // 0:noise_b 1:noise_cnt 2:cc 3:pot 4:beta+pay 6:nobj
__device__ unsigned g_ticket;

// ---------------- helpers ----------------
__device__ __forceinline__ float softclipf(float x, float s) {
    float y = x / s;
    y = (y > 1.0f) ? logf(y + 1.0f) : y;
    return y * s;
}
__device__ __forceinline__ float huberf(float x, float d) {
    float ax = fabsf(x);
    return (ax < d) ? x * x : d * d + 2.0f * d * (ax - d);
}
__device__ __forceinline__ float warpSum(float v) {
    #pragma unroll
    for (int o = 16; o > 0; o >>= 1) v += __shfl_down_sync(0xffffffffu, v, o);
    return v;
}
__device__ __forceinline__ float sqrt_approx(float x) {
    float r;
    asm("sqrt.approx.f32 %0, %1;" : "=f"(r) : "f"(x));
    return r;
}

// ---------------- phase 1: per-hit pass ----------------
__global__ void __launch_bounds__(256) k_phase1(
    const float* __restrict__ pb, const float2* __restrict__ cc,
    const float* __restrict__ pE, const float2* __restrict__ pPos,
    const float* __restrict__ pT, const float* __restrict__ pId,
    const int*   __restrict__ tIdx, const float* __restrict__ tE,
    const float2* __restrict__ tPos, const float* __restrict__ tT)
{
    int n = blockIdx.x * blockDim.x + threadIdx.x;
    int rep = blockIdx.x & (NREP - 1);
    float nb = 0.0f, ncnt = 0.0f, ccs = 0.0f;
    if (n < NHITS) {
        float b = fminf(fmaxf(pb[n], 1e-6f), 1.0f - 1e-6f);
        float at = atanhf(b);
        float q = at * at + 0.1f;
        g_q[n] = q;
        float2 c = cc[n];
        ccs = fmaf(c.x, c.x, c.y * c.y);
        int t = tIdx[n];
        if (t >= 0) {
            atomicAdd(&g_cnt[rep][t], 1);
            unsigned long long pk =
                ((unsigned long long)__float_as_uint(b) << 32) |
                (unsigned long long)(0xFFFFFFFFu - (unsigned)n);
            atomicMax(&g_packed[rep][t], pk);
            float te = tE[n];
            float ed = fabsf(te - pE[n]);
            float le = 10.0f * expf(-0.1f * ed * ed) + 0.01f * ed;
            le = softclipf(le, 10.0f);
            float2 tp = tPos[n], pp = pPos[n];
            float dpx = tp.x - pp.x, dpy = tp.y - pp.y;
            float d2p = fmaf(dpx, dpx, dpy * dpy);
            float pl = softclipf(huberf(sqrtf(d2p * 0.01f + 0.01f), 10.0f), 3.0f);
            float tl = softclipf(huberf(tT[n] - pT[n], 2.0f), 6.0f);
            float cls = 0.0f;
            #pragma unroll
            for (int j = 0; j < 6; j++) { float v = pId[6 * n + j]; cls += v * v; }
            cls *= (1e-8f / 6.0f);
            float payload = le + pl + tl + cls;
            float ew = (te > 10.0f) ? 1.0f : fmaxf((te - 0.5f) * (1.0f / 9.5f), 0.0f);
            float pw = b * ew;
            atomicAdd(&g_num[rep][t], payload * pw);
            atomicAdd(&g_den[rep][t], pw);
        } else {
            nb = b; ncnt = 1.0f;
        }
    }
    __shared__ float sr[3][8];
    float w0 = warpSum(nb), w1 = warpSum(ncnt), w2 = warpSum(ccs);
    int lane = threadIdx.x & 31, wid = threadIdx.x >> 5;
    if (lane == 0) { sr[0][wid] = w0; sr[1][wid] = w1; sr[2][wid] = w2; }
    __syncthreads();
    if (wid == 0) {
        float v0 = (lane < 8) ? sr[0][lane] : 0.0f;
        float v1 = (lane < 8) ? sr[1][lane] : 0.0f;
        float v2 = (lane < 8) ? sr[2][lane] : 0.0f;
        v0 = warpSum(v0); v1 = warpSum(v1); v2 = warpSum(v2);
        if (lane == 0) {
            if (v1 != 0.0f || v0 != 0.0f) {
                atomicAdd(&g_scal[0], v0);
                atomicAdd(&g_scal[1], v1);
            }
            atomicAdd(&g_scal[2], v2);
        }
    }
}

// ---------------- phase 2: reduce replicas, build per-object data ----------
__global__ void __launch_bounds__(128) k_phase2(const float2* __restrict__ cc) {
    int k = blockIdx.x * 128 + threadIdx.x;
    int cnt = 0;
    float num = 0.0f, den = 0.0f;
    unsigned long long pk = 0ull;
    #pragma unroll
    for (int r = 0; r < NREP; r++) {
        cnt += g_cnt[r][k];
        num += g_num[r][k];
        den += g_den[r][k];
        unsigned long long p = g_packed[r][k];
        pk = (p > pk) ? p : pk;
    }
    float4 o = make_float4(0.0f, 0.0f, 1e6f, 0.0f);
    float aw = 0.0f, part = 0.0f, nob = 0.0f;
    if (cnt > 0) {
        float betaA = __uint_as_float((unsigned)(pk >> 32));
        unsigned alpha = 0xFFFFFFFFu - (unsigned)(pk & 0xFFFFFFFFull);
        float2 c = cc[alpha];
        float at = atanhf(betaA);
        float qa = at * at + 0.1f;
        o.x = -2.0f * c.x;
        o.y = -2.0f * c.y;
        o.z = fmaf(c.x, c.x, c.y * c.y) + 1e-6f;
        o.w = qa / ((float)NHITS - (float)cnt + EPSF);
        aw  = qa / ((float)cnt + EPSF);
        part = (1.0f - betaA) + num / (den + EPSF);
        nob = 1.0f;
    }
    g_obj[k] = o;
    g_attw[k] = aw;
    __shared__ float sp[4], sn[4];
    float w0 = warpSum(part), w1 = warpSum(nob);
    int lane = threadIdx.x & 31, wid = threadIdx.x >> 5;
    if (lane == 0) { sp[wid] = w0; sn[wid] = w1; }
    __syncthreads();
    if (threadIdx.x == 0) {
        float v0 = sp[0] + sp[1] + sp[2] + sp[3];
        float v1 = sn[0] + sn[1] + sn[2] + sn[3];
        atomicAdd(&g_scal[4], v0);
        atomicAdd(&g_scal[6], v1);
    }
}

// ---------------- phase 3: dense N x KCHUNK + zero + finalize -------------
__global__ void __launch_bounds__(256) k_phase3(
    const float2* __restrict__ cc, const int* __restrict__ tIdx,
    float* __restrict__ out)
{
    __shared__ float4 sobj[KCHUNK];
    const int kbase = blockIdx.y * KCHUNK;
    if (threadIdx.x < KCHUNK) sobj[threadIdx.x] = g_obj[kbase + threadIdx.x];

    // distributed re-zero of the replicated scratch (phase2 already consumed it)
    {
        int lin = blockIdx.y * NBX + blockIdx.x;
        if (threadIdx.x < ZERO_PER_BLOCK) {
            int idx = lin * ZERO_PER_BLOCK + threadIdx.x;
            if (idx < SCRATCH_TOT) {
                ((int*)g_cnt)[idx] = 0;
                ((float*)g_num)[idx] = 0.0f;
                ((float*)g_den)[idx] = 0.0f;
                ((unsigned long long*)g_packed)[idx] = 0ull;
            }
        }
    }
    __syncthreads();

    int n = blockIdx.x * blockDim.x + threadIdx.x;
    float res = 0.0f;
    if (n < NHITS) {
        float2 c = cc[n];
        float x = c.x, y = c.y;
        float q = g_q[n];
        float h = fmaf(x, x, y * y);
        float a0 = 0.0f, a1 = 0.0f, a2 = 0.0f, a3 = 0.0f;
        #pragma unroll 4
        for (int k = 0; k < KCHUNK; k += 4) {
            {
                float4 o = sobj[k];
                float t = fmaf(o.x, x, o.z); t = fmaf(o.y, y, t);
                float d = sqrt_approx(h + t);
                a0 = fmaf(fmaxf(1.0f - d, 0.0f), o.w, a0);
            }
            {
                float4 o = sobj[k + 1];
                float t = fmaf(o.x, x, o.z); t = fmaf(o.y, y, t);
                float d = sqrt_approx(h + t);
                a1 = fmaf(fmaxf(1.0f - d, 0.0f), o.w, a1);
            }
            {
                float4 o = sobj[k + 2];
                float t = fmaf(o.x, x, o.z); t = fmaf(o.y, y, t);
                float d = sqrt_approx(h + t);
                a2 = fmaf(fmaxf(1.0f - d, 0.0f), o.w, a2);
            }
            {
                float4 o = sobj[k + 3];
                float t = fmaf(o.x, x, o.z); t = fmaf(o.y, y, t);
                float d = sqrt_approx(h + t);
                a3 = fmaf(fmaxf(1.0f - d, 0.0f), o.w, a3);
            }
        }
        res = ((a0 + a1) + (a2 + a3)) * q;
        int t = tIdx[n];
        if (t >= kbase && t < kbase + KCHUNK) {
            float4 o = sobj[t - kbase];
            float dx = fmaf(0.5f, o.x, x);
            float dy = fmaf(0.5f, o.y, y);
            float d2n = fmaf(dx, dx, dy * dy);
            float d = sqrt_approx(d2n + 1e-6f);
            res -= fmaxf(1.0f - d, 0.0f) * o.w * q;
            res = fmaf(d2n * g_attw[t], q, res);
        }
    }
    __shared__ float sr[8];
    float w = warpSum(res);
    int lane = threadIdx.x & 31, wid = threadIdx.x >> 5;
    if (lane == 0) sr[wid] = w;
    __syncthreads();
    __shared__ bool isLast;
    if (threadIdx.x == 0) isLast = false;
    if (wid == 0) {
        float v = (lane < 8) ? sr[lane] : 0.0f;
        v = warpSum(v);
        if (lane == 0) {
            atomicAdd(&g_scal[3], v);
            __threadfence();
            unsigned tk = atomicAdd(&g_ticket, 1u);
            isLast = (tk == (unsigned)(TOTAL_P3_BLOCKS - 1));
        }
    }
    __syncthreads();
    if (isLast) {
        if (threadIdx.x == 0) {
            float inv = 1.0f / (g_scal[6] + EPSF);
            float total = (g_scal[3] + g_scal[4]) * inv
                        + g_scal[0] / (g_scal[1] + EPSF)
                        + 0.001f * g_scal[2] * (1.0f / ((float)NHITS * 2.0f));
            out[0] = total;
            g_ticket = 0;
        }
        __syncthreads();
        if (threadIdx.x < 8) g_scal[threadIdx.x] = 0.0f;
    }
}

// ---------------- launch ----------------
extern "C" void kernel_launch(void* const* d_in, const int* in_sizes, int n_in,
                              void* d_out, int out_size)
{
    const float*  pb   = (const float*) d_in[0];
    const float2* cc   = (const float2*)d_in[1];
    const float*  pE   = (const float*) d_in[2];
    const float2* pPos = (const float2*)d_in[3];
    const float*  pT   = (const float*) d_in[4];
    const float*  pId  = (const float*) d_in[5];
    const int*    tIdx = (const int*)   d_in[6];
    const float*  tE   = (const float*) d_in[7];
    const float2* tPos = (const float2*)d_in[8];
    const float*  tT   = (const float*) d_in[9];
    float* out = (float*)d_out;

    k_phase1<<<NBX, 256>>>(pb, cc, pE, pPos, pT, pId, tIdx, tE, tPos, tT);
    k_phase2<<<KOBJ / 128, 128>>>(cc);
    dim3 g3(NBX, NCHUNK);
    k_phase3<<<g3, 256>>>(cc, tIdx, out);
}

// round 6
// speedup vs baseline: 1.7116x; 1.0702x over previous
#include <cuda_runtime.h>
#include <cstdint>

#define NHITS 80000
#define KOBJ  512
#define NREP  32
#define KCHUNK 64
#define NCHUNK (KOBJ / KCHUNK)
#define EPSF  1e-9f

#define NBX 313               // ceil(80000/256)
#define TOTAL_P3_BLOCKS (NBX * NCHUNK)
#define SCRATCH_TOT (NREP * KOBJ)
#define ZERO_PER_BLOCK ((SCRATCH_TOT + TOTAL_P3_BLOCKS - 1) / TOTAL_P3_BLOCKS)

// ---------------- device scratch (zero at load; re-zeroed by phase3 each run)
__device__ unsigned long long g_packed[NREP][KOBJ];
__device__ int    g_cnt[NREP][KOBJ];
__device__ float  g_num[NREP][KOBJ];
__device__ float  g_den[NREP][KOBJ];
__device__ float  g_q[NHITS];
__device__ float4 g_pA[KOBJ / 2];   // (m2ox_j, m2ox_j1, m2oy_j, m2oy_j1)
__device__ float4 g_pB[KOBJ / 2];   // (ozeps_j, ozeps_j1, w_j, w_j1)
__device__ float  g_attw[KOBJ];
__device__ float  g_wsum[NCHUNK];   // per-chunk sum of repulsion weights
__device__ float  g_scal[8];        // 0:noise_b 1:noise_cnt 2:cc 3:pot 4:beta+pay 6:nobj
__device__ unsigned g_ticket;

// ---------------- helpers ----------------
__device__ __forceinline__ float softclipf(float x, float s) {
    float y = x / s;
    y = (y > 1.0f) ? __logf(y + 1.0f) : y;
    return y * s;
}
__device__ __forceinline__ float huberf(float x, float d) {
    float ax = fabsf(x);
    return (ax < d) ? x * x : d * d + 2.0f * d * (ax - d);
}
__device__ __forceinline__ float warpSum(float v) {
    #pragma unroll
    for (int o = 16; o > 0; o >>= 1) v += __shfl_down_sync(0xffffffffu, v, o);
    return v;
}
__device__ __forceinline__ float sqrt_approx(float x) {
    float r;
    asm("sqrt.approx.f32 %0, %1;" : "=f"(r) : "f"(x));
    return r;
}
__device__ __forceinline__ float fast_atanh(float b) {
    return 0.5f * __logf(__fdividef(1.0f + b, 1.0f - b));
}
// packed f32x2 helpers
__device__ __forceinline__ unsigned long long pk2(float lo, float hi) {
    unsigned long long r;
    asm("mov.b64 %0, {%1, %2};" : "=l"(r) : "f"(lo), "f"(hi));
    return r;
}
__device__ __forceinline__ void unpk2(unsigned long long v, float& lo, float& hi) {
    asm("mov.b64 {%0, %1}, %2;" : "=f"(lo), "=f"(hi) : "l"(v));
}
__device__ __forceinline__ unsigned long long fma2_(unsigned long long a,
                                                    unsigned long long b,
                                                    unsigned long long c) {
    unsigned long long r;
    asm("fma.rn.f32x2 %0, %1, %2, %3;" : "=l"(r) : "l"(a), "l"(b), "l"(c));
    return r;
}
__device__ __forceinline__ unsigned long long add2_(unsigned long long a,
                                                    unsigned long long b) {
    unsigned long long r;
    asm("add.rn.f32x2 %0, %1, %2;" : "=l"(r) : "l"(a), "l"(b));
    return r;
}

// ---------------- phase 1: per-hit pass ----------------
__global__ void __launch_bounds__(256) k_phase1(
    const float* __restrict__ pb, const float2* __restrict__ cc,
    const float* __restrict__ pE, const float2* __restrict__ pPos,
    const float* __restrict__ pT, const float2* __restrict__ pId2,
    const int*   __restrict__ tIdx, const float* __restrict__ tE,
    const float2* __restrict__ tPos, const float* __restrict__ tT)
{
    int n = blockIdx.x * blockDim.x + threadIdx.x;
    int rep = blockIdx.x & (NREP - 1);
    float nb = 0.0f, ncnt = 0.0f, ccs = 0.0f;
    if (n < NHITS) {
        float b = fminf(fmaxf(pb[n], 1e-6f), 1.0f - 1e-6f);
        float at = fast_atanh(b);
        float q = fmaf(at, at, 0.1f);
        g_q[n] = q;
        float2 c = cc[n];
        ccs = fmaf(c.x, c.x, c.y * c.y);
        int t = tIdx[n];
        if (t >= 0) {
            atomicAdd(&g_cnt[rep][t], 1);
            unsigned long long pk =
                ((unsigned long long)__float_as_uint(b) << 32) |
                (unsigned long long)(0xFFFFFFFFu - (unsigned)n);
            atomicMax(&g_packed[rep][t], pk);
            float te = tE[n];
            float ed = fabsf(te - pE[n]);
            float le = 10.0f * __expf(-0.1f * ed * ed) + 0.01f * ed;
            le = softclipf(le, 10.0f);
            float2 tp = tPos[n], pp = pPos[n];
            float dpx = tp.x - pp.x, dpy = tp.y - pp.y;
            float d2p = fmaf(dpx, dpx, dpy * dpy);
            float pl = softclipf(huberf(sqrt_approx(fmaf(d2p, 0.01f, 0.01f)), 10.0f), 3.0f);
            float tl = softclipf(huberf(tT[n] - pT[n], 2.0f), 6.0f);
            float2 i0 = pId2[3 * n], i1 = pId2[3 * n + 1], i2 = pId2[3 * n + 2];
            float cls = i0.x * i0.x + i0.y * i0.y + i1.x * i1.x
                      + i1.y * i1.y + i2.x * i2.x + i2.y * i2.y;
            cls *= (1e-8f / 6.0f);
            float payload = le + pl + tl + cls;
            float ew = (te > 10.0f) ? 1.0f : fmaxf((te - 0.5f) * (1.0f / 9.5f), 0.0f);
            float pw = b * ew;
            atomicAdd(&g_num[rep][t], payload * pw);
            atomicAdd(&g_den[rep][t], pw);
        } else {
            nb = b; ncnt = 1.0f;
        }
    }
    __shared__ float sr[3][8];
    float w0 = warpSum(nb), w1 = warpSum(ncnt), w2 = warpSum(ccs);
    int lane = threadIdx.x & 31, wid = threadIdx.x >> 5;
    if (lane == 0) { sr[0][wid] = w0; sr[1][wid] = w1; sr[2][wid] = w2; }
    __syncthreads();
    if (wid == 0) {
        float v0 = (lane < 8) ? sr[0][lane] : 0.0f;
        float v1 = (lane < 8) ? sr[1][lane] : 0.0f;
        float v2 = (lane < 8) ? sr[2][lane] : 0.0f;
        v0 = warpSum(v0); v1 = warpSum(v1); v2 = warpSum(v2);
        if (lane == 0) {
            if (v1 != 0.0f || v0 != 0.0f) {
                atomicAdd(&g_scal[0], v0);
                atomicAdd(&g_scal[1], v1);
            }
            atomicAdd(&g_scal[2], v2);
        }
    }
}

// ---------------- phase 2: reduce replicas, build packed object data -------
__global__ void __launch_bounds__(128) k_phase2(const float2* __restrict__ cc) {
    int k = blockIdx.x * 128 + threadIdx.x;
    int cnt = 0;
    float num = 0.0f, den = 0.0f;
    unsigned long long pk = 0ull;
    #pragma unroll
    for (int r = 0; r < NREP; r++) {
        cnt += g_cnt[r][k];
        num += g_num[r][k];
        den += g_den[r][k];
        unsigned long long p = g_packed[r][k];
        pk = (p > pk) ? p : pk;
    }
    float m2ox = 0.0f, m2oy = 0.0f, ozeps = 1e6f, w = 0.0f;
    float aw = 0.0f, part = 0.0f, nob = 0.0f;
    if (cnt > 0) {
        float betaA = __uint_as_float((unsigned)(pk >> 32));
        unsigned alpha = 0xFFFFFFFFu - (unsigned)(pk & 0xFFFFFFFFull);
        float2 c = cc[alpha];
        float at = fast_atanh(betaA);
        float qa = fmaf(at, at, 0.1f);
        m2ox = -2.0f * c.x;
        m2oy = -2.0f * c.y;
        ozeps = fmaf(c.x, c.x, c.y * c.y) + 1e-6f;
        w  = qa / ((float)NHITS - (float)cnt + EPSF);
        aw = qa / ((float)cnt + EPSF);
        part = (1.0f - betaA) + num / (den + EPSF);
        nob = 1.0f;
    }
    int pr = k >> 1, hf = k & 1;
    float* pA = (float*)g_pA;
    float* pB = (float*)g_pB;
    pA[pr * 4 + hf]     = m2ox;
    pA[pr * 4 + 2 + hf] = m2oy;
    pB[pr * 4 + hf]     = ozeps;
    pB[pr * 4 + 2 + hf] = w;
    g_attw[k] = aw;
    // per-chunk weight sum (warp-uniform chunk index: 32 consecutive k share k>>6)
    float ws = warpSum(w);
    int lane = threadIdx.x & 31, wid = threadIdx.x >> 5;
    if (lane == 0) atomicAdd(&g_wsum[k >> 6], ws);
    __shared__ float sp[4], sn[4];
    float w0 = warpSum(part), w1 = warpSum(nob);
    if (lane == 0) { sp[wid] = w0; sn[wid] = w1; }
    __syncthreads();
    if (threadIdx.x == 0) {
        atomicAdd(&g_scal[4], sp[0] + sp[1] + sp[2] + sp[3]);
        atomicAdd(&g_scal[6], sn[0] + sn[1] + sn[2] + sn[3]);
    }
}

// ---------------- phase 3: dense N x KCHUNK (packed) + zero + finalize -----
__global__ void __launch_bounds__(256) k_phase3(
    const float2* __restrict__ cc, const int* __restrict__ tIdx,
    float* __restrict__ out)
{
    __shared__ float4 sA[KCHUNK / 2];
    __shared__ float4 sB[KCHUNK / 2];
    const int kbase = blockIdx.y * KCHUNK;
    if (threadIdx.x < KCHUNK / 2) {
        sA[threadIdx.x] = g_pA[kbase / 2 + threadIdx.x];
        sB[threadIdx.x] = g_pB[kbase / 2 + threadIdx.x];
    }
    // distributed re-zero of the replicated scratch
    {
        int lin = blockIdx.y * NBX + blockIdx.x;
        if (threadIdx.x < ZERO_PER_BLOCK) {
            int idx = lin * ZERO_PER_BLOCK + threadIdx.x;
            if (idx < SCRATCH_TOT) {
                ((int*)g_cnt)[idx] = 0;
                ((float*)g_num)[idx] = 0.0f;
                ((float*)g_den)[idx] = 0.0f;
                ((unsigned long long*)g_packed)[idx] = 0ull;
            }
        }
    }
    __syncthreads();

    int n = blockIdx.x * blockDim.x + threadIdx.x;
    float res = 0.0f;
    if (n < NHITS) {
        float2 c = cc[n];
        float x = c.x, y = c.y;
        float q = g_q[n];
        float h = fmaf(x, x, y * y);
        unsigned long long XX = pk2(x, x), YY = pk2(y, y), HH = pk2(h, h);
        float acc0 = 0.0f, acc1 = 0.0f;
        const ulonglong2* A2 = (const ulonglong2*)sA;
        const ulonglong2* B2 = (const ulonglong2*)sB;
        #pragma unroll 8
        for (int p = 0; p < KCHUNK / 2; p += 2) {
            {
                ulonglong2 A = A2[p];
                ulonglong2 B = B2[p];
                unsigned long long t = fma2_(A.y, YY, B.x);
                t = fma2_(A.x, XX, t);
                t = add2_(t, HH);
                float d2a, d2b; unpk2(t, d2a, d2b);
                float da = sqrt_approx(d2a), db = sqrt_approx(d2b);
                float wa, wb; unpk2(B.y, wa, wb);
                acc0 = fmaf(wa, fminf(da, 1.0f), acc0);
                acc0 = fmaf(wb, fminf(db, 1.0f), acc0);
            }
            {
                ulonglong2 A = A2[p + 1];
                ulonglong2 B = B2[p + 1];
                unsigned long long t = fma2_(A.y, YY, B.x);
                t = fma2_(A.x, XX, t);
                t = add2_(t, HH);
                float d2a, d2b; unpk2(t, d2a, d2b);
                float da = sqrt_approx(d2a), db = sqrt_approx(d2b);
                float wa, wb; unpk2(B.y, wa, wb);
                acc1 = fmaf(wa, fminf(da, 1.0f), acc1);
                acc1 = fmaf(wb, fminf(db, 1.0f), acc1);
            }
        }
        // sum_k w*relu(1-d) = Wsum_chunk - sum_k w*min(d,1)
        res = (g_wsum[blockIdx.y] - (acc0 + acc1)) * q;
        int t = tIdx[n];
        if (t >= kbase && t < kbase + KCHUNK) {
            int j = t - kbase;
            int pr = j >> 1, hf = j & 1;
            float4 Af = sA[pr], Bf = sB[pr];
            float m2ox = hf ? Af.y : Af.x;
            float m2oy = hf ? Af.w : Af.z;
            float w    = hf ? Bf.w : Bf.z;
            float dx = fmaf(0.5f, m2ox, x);
            float dy = fmaf(0.5f, m2oy, y);
            float d2n = fmaf(dx, dx, dy * dy);
            float d = sqrt_approx(d2n + 1e-6f);
            res -= fmaxf(1.0f - d, 0.0f) * w * q;
            res = fmaf(d2n * g_attw[t], q, res);
        }
    }
    __shared__ float sr[8];
    float wv = warpSum(res);
    int lane = threadIdx.x & 31, wid = threadIdx.x >> 5;
    if (lane == 0) sr[wid] = wv;
    __syncthreads();
    __shared__ bool isLast;
    if (threadIdx.x == 0) isLast = false;
    if (wid == 0) {
        float v = (lane < 8) ? sr[lane] : 0.0f;
        v = warpSum(v);
        if (lane == 0) {
            atomicAdd(&g_scal[3], v);
            __threadfence();
            unsigned tk = atomicAdd(&g_ticket, 1u);
            isLast = (tk == (unsigned)(TOTAL_P3_BLOCKS - 1));
        }
    }
    __syncthreads();
    if (isLast) {
        if (threadIdx.x == 0) {
            float inv = 1.0f / (g_scal[6] + EPSF);
            float total = (g_scal[3] + g_scal[4]) * inv
                        + g_scal[0] / (g_scal[1] + EPSF)
                        + 0.001f * g_scal[2] * (1.0f / ((float)NHITS * 2.0f));
            out[0] = total;
            g_ticket = 0;
        }
        __syncthreads();
        if (threadIdx.x < 8) {
            g_scal[threadIdx.x] = 0.0f;
            g_wsum[threadIdx.x] = 0.0f;
        }
    }
}

// ---------------- launch ----------------
extern "C" void kernel_launch(void* const* d_in, const int* in_sizes, int n_in,
                              void* d_out, int out_size)
{
    const float*  pb   = (const float*) d_in[0];
    const float2* cc   = (const float2*)d_in[1];
    const float*  pE   = (const float*) d_in[2];
    const float2* pPos = (const float2*)d_in[3];
    const float*  pT   = (const float*) d_in[4];
    const float2* pId2 = (const float2*)d_in[5];
    const int*    tIdx = (const int*)   d_in[6];
    const float*  tE   = (const float*) d_in[7];
    const float2* tPos = (const float2*)d_in[8];
    const float*  tT   = (const float*) d_in[9];
    float* out = (float*)d_out;

    k_phase1<<<NBX, 256>>>(pb, cc, pE, pPos, pT, pId2, tIdx, tE, tPos, tT);
    k_phase2<<<KOBJ / 128, 128>>>(cc);
    dim3 g3(NBX, NCHUNK);
    k_phase3<<<g3, 256>>>(cc, tIdx, out);
}